// round 11
// baseline (speedup 1.0000x reference)
#include <cuda_runtime.h>
#include <cuda_bf16.h>
#include <cooperative_groups.h>
#include <math.h>

namespace cg = cooperative_groups;

#define S_SPK   2
#define BB      16
#define TT      300
#define CC      3000
#define NSTATES 400
#define NARCS   1200
#define DSTATES 3000
#define DARCS   60000
#define NPAIR   (S_SPK * BB)        // 32
#define CLUSTER 4
#define SLICE   (DSTATES / CLUSTER) // 750
#define FWD_THREADS 768
#define NWARPS  (FWD_THREADS / 32)  // 24
#define NHALF   (NSTATES / 2)       // 200
#define CAP_D   18432               // smem arc cache cap (den slice, padded col-major)
#define CAP_N   1024                // smem arc cache cap (num half)
#define LN2 0.6931471805599453

// ---------------- device scratch (static globals, no allocation) ----------------
__device__ int   g_den_hist[DSTATES];
__device__ int   g_den_rowptr[DSTATES + 1];
__device__ uint2 g_den_arcs[DARCS + 4];              // +4 zeroed pad
__device__ int   g_den_order[DSTATES];               // newid -> oldid (desc arc count per slice)
__device__ int   g_den_inv[DSTATES];                 // oldid -> newid

__device__ int   g_num_rowptr[NPAIR][NSTATES + 1];
__device__ uint2 g_num_arcs[NPAIR * NARCS + 4];      // +4 zeroed pad

__device__ float g_denZ[NPAIR];              // [s*BB + b]
__device__ float g_numZ[S_SPK][S_SPK][BB];   // [speaker s][graph g][b]

// ---------------- prep kernel 1: zero hist + pads ----------------
__global__ void k_prep_zero() {
    int i = blockIdx.x * blockDim.x + threadIdx.x;
    if (i < DSTATES) g_den_hist[i] = 0;
    if (i < 4) {
        g_den_arcs[DARCS + i] = make_uint2(0u, 0u);
        g_num_arcs[NPAIR * NARCS + i] = make_uint2(0u, 0u);
    }
}

// ---------------- prep kernel 2: den histogram ----------------
__global__ void k_den_hist(const int* __restrict__ dst) {
    int i = blockIdx.x * blockDim.x + threadIdx.x;
    if (i < DARCS) atomicAdd(&g_den_hist[dst[i]], 1);
}

// ---------------- prep kernel 3 (fused): den scan+scatter+order (CTA 0) + num prep ----
__global__ void __launch_bounds__(1024, 1)
k_prep_rest(const int* __restrict__ dsrc, const int* __restrict__ ddst,
            const int* __restrict__ dlab, const float* __restrict__ dw,
            const int* __restrict__ nsrc, const int* __restrict__ ndst,
            const int* __restrict__ nlab, const float* __restrict__ nw) {
    int tid = threadIdx.x;
    if (blockIdx.x == 0) {
        __shared__ int ssum[1024];
        __shared__ int cur[DSTATES];
        __shared__ int hist4[4 * 128];
        __shared__ int cur4[4 * 128];
        int base = tid * 3;
        int a = 0, b = 0, c = 0;
        if (base     < DSTATES) a = g_den_hist[base];
        if (base + 1 < DSTATES) b = g_den_hist[base + 1];
        if (base + 2 < DSTATES) c = g_den_hist[base + 2];
        int local = a + b + c;
        ssum[tid] = local;
        __syncthreads();
        for (int off = 1; off < 1024; off <<= 1) {
            int v = (tid >= off) ? ssum[tid - off] : 0;
            __syncthreads();
            ssum[tid] += v;
            __syncthreads();
        }
        int excl = ssum[tid] - local;
        if (base < DSTATES)     { g_den_rowptr[base]     = excl;         cur[base]     = excl; }
        if (base + 1 < DSTATES) { g_den_rowptr[base + 1] = excl + a;     cur[base + 1] = excl + a; }
        if (base + 2 < DSTATES) { g_den_rowptr[base + 2] = excl + a + b; cur[base + 2] = excl + a + b; }
        if (tid == 1023) g_den_rowptr[DSTATES] = ssum[1023];
        if (tid < 512) { hist4[tid] = 0; }
        __syncthreads();
        for (int i = tid; i < DARCS; i += 1024) {
            int d = ddst[i];
            int pos = atomicAdd(&cur[d], 1);
            g_den_arcs[pos] = make_uint2((unsigned)dsrc[i] | ((unsigned)dlab[i] << 16),
                                         __float_as_uint(expf(dw[i])));
        }
        for (int i = tid; i < DSTATES; i += 1024) {
            int cnt = g_den_rowptr[i + 1] - g_den_rowptr[i];
            if (cnt > 127) cnt = 127;
            int slc = i / SLICE;
            atomicAdd(&hist4[slc * 128 + (127 - cnt)], 1);
        }
        __syncthreads();
        if (tid < 4) {
            int acc = 0;
            for (int k = 0; k < 128; ++k) { cur4[tid * 128 + k] = acc; acc += hist4[tid * 128 + k]; }
        }
        __syncthreads();
        for (int i = tid; i < DSTATES; i += 1024) {
            int cnt = g_den_rowptr[i + 1] - g_den_rowptr[i];
            if (cnt > 127) cnt = 127;
            int slc = i / SLICE;
            int pos = atomicAdd(&cur4[slc * 128 + (127 - cnt)], 1);
            int newid = slc * SLICE + pos;
            g_den_order[newid] = i;
            g_den_inv[i] = newid;
        }
    } else {
        int gb = blockIdx.x - 1;
        const int*   s_ = nsrc + gb * NARCS;
        const int*   d_ = ndst + gb * NARCS;
        const int*   l_ = nlab + gb * NARCS;
        const float* w_ = nw   + gb * NARCS;
        __shared__ int hist[1024];
        __shared__ int scan2[1024];
        __shared__ int ncur[NSTATES];
        hist[tid] = 0;
        __syncthreads();
        for (int i = tid; i < NARCS; i += 1024) atomicAdd(&hist[d_[i]], 1);
        __syncthreads();
        int local = hist[tid];
        scan2[tid] = local;
        __syncthreads();
        for (int off = 1; off < 1024; off <<= 1) {
            int v = (tid >= off) ? scan2[tid - off] : 0;
            __syncthreads();
            scan2[tid] += v;
            __syncthreads();
        }
        int excl = scan2[tid] - local;
        if (tid < NSTATES) { g_num_rowptr[gb][tid] = excl; ncur[tid] = excl; }
        if (tid == NSTATES) g_num_rowptr[gb][NSTATES] = NARCS;
        __syncthreads();
        for (int i = tid; i < NARCS; i += 1024) {
            int d = d_[i];
            int pos = atomicAdd(&ncur[d], 1);
            g_num_arcs[gb * NARCS + pos] =
                make_uint2((unsigned)s_[i] | ((unsigned)l_[i] << 16), __float_as_uint(expf(w_[i])));
        }
    }
}

// ---------------- fused forward ----------------
// dynamic smem layout (float indices; uint2 caches 8B-aligned):
#define SM_PD    0                        // [2][DSTATES]   (NEW state numbering)
#define SM_FR    (2 * DSTATES)            // [2][CC]
#define SM_PN    (SM_FR + 2 * CC)         // [2][NSTATES]
#define SM_REDD  (SM_PN + 2 * NSTATES)    // [24]
#define SM_REDN  (SM_REDD + 24)           // [24]
#define SM_PMAX  (SM_REDN + 24)           // [2][4]
#define SM_BCN   (SM_PMAX + 8)            // [2][2]
#define SM_WB    (SM_BCN + 4)             // [NWARPS+2]  warp col-major bases (+total)
#define SM_DARC  (SM_WB + NWARPS + 2)     // uint2[CAP_D] col-major warp-interleaved
#define SM_NARC  (SM_DARC + 2 * CAP_D)    // uint2[CAP_N+4]
#define SM_FLOATS (SM_NARC + 2 * (CAP_N + 4))
#define SMEM_FWD_BYTES (SM_FLOATS * 4)

__global__ void __launch_bounds__(FWD_THREADS, 1) __cluster_dims__(CLUSTER, 1, 1)
k_forward(const float* __restrict__ llhs, const int* __restrict__ seqlen,
          const float* __restrict__ den_start, const float* __restrict__ den_final,
          const float* __restrict__ num_start, const float* __restrict__ num_final) {
    extern __shared__ float sm[];
    float* pd   = sm + SM_PD;
    float* fr   = sm + SM_FR;
    float* pn   = sm + SM_PN;
    float* redd = sm + SM_REDD;
    float* redn = sm + SM_REDN;
    float* pmax = sm + SM_PMAX;
    float* bcn  = sm + SM_BCN;
    int*   wb   = (int*)(sm + SM_WB);
    uint2* sda  = (uint2*)(sm + SM_DARC);
    uint2* sna  = (uint2*)(sm + SM_NARC);

    cg::cluster_group cl = cg::this_cluster();
    unsigned rank = cl.block_rank();
    int pair = blockIdx.x >> 2;
    int s = pair >> 4, b = pair & 15;
    const float* llh = llhs + (size_t)pair * TT * CC;
    int Tb = seqlen[b];
    int tid = threadIdx.x;
    int lane = tid & 31, wid = tid >> 5;
    int g    = (int)rank & 1;
    int half = (int)rank >> 1;
    int gb   = g * BB + b;
    int prank = (int)rank ^ 2;

    float* rb[CLUSTER];
    #pragma unroll
    for (int r = 0; r < CLUSTER; ++r) rb[r] = cl.map_shared_rank(sm, r);

    // ---- prologue ----
    for (int i = tid; i < DSTATES; i += FWD_THREADS)
        pd[i] = __expf(den_start[g_den_order[i]]);
    for (int i = tid; i < NSTATES; i += FWD_THREADS)
        pn[i] = __expf(num_start[gb * NSTATES + i]);
    if (tid < 8) pmax[tid] = 1.0f;
    if (tid < 4) bcn[tid]  = 1.0f;
    for (int i = tid; i < CC; i += FWD_THREADS) fr[i] = __expf(llh[i]);

    int mynew = (int)rank * SLICE + tid;
    int dbeg = 0, dend = 0;
    if (tid < SLICE) {
        int myold = g_den_order[mynew];
        dbeg = g_den_rowptr[myold];
        dend = g_den_rowptr[myold + 1];
    }
    int dcnt = dend - dbeg;              // 0 for tid >= SLICE
    int nst = half * NHALF + tid;
    int nbeg = 0, nend = 0;
    if (tid < NHALF) { nbeg = g_num_rowptr[gb][nst]; nend = g_num_rowptr[gb][nst + 1]; }

    // ---- per-warp column-major layout: maxcount (padded to 4), exclusive scan ----
    int mc = dcnt;
    #pragma unroll
    for (int o = 16; o; o >>= 1) mc = max(mc, __shfl_xor_sync(0xffffffffu, mc, o));
    int mcp = (mc + 3) & ~3;
    if (lane == 0) wb[wid] = mcp;
    __syncthreads();
    if (tid < 32) {
        int v = (tid < NWARPS) ? wb[tid] : 0;
        int x = v;
        #pragma unroll
        for (int o = 1; o < 32; o <<= 1) {
            int y = __shfl_up_sync(0xffffffffu, x, o);
            if (lane >= o) x += y;
        }
        if (tid < NWARPS) wb[tid] = (x - v) * 32;       // base in arc slots
        if (tid == NWARPS - 1) wb[NWARPS] = x * 32;     // total slots
    }
    __syncthreads();
    int wbase = wb[wid];
    int dtotal = wb[NWARPS];
    bool d_insmem = (dtotal <= CAP_D);

    // ---- zero the col-major region (pad slots must be index-0/weight-0) ----
    if (d_insmem) {
        for (int i = tid; i < dtotal; i += FWD_THREADS) sda[i] = make_uint2(0u, 0u);
    }
    __syncthreads();
    // ---- stage den arcs col-major, remapping src to new ids ----
    if (d_insmem && tid < SLICE) {
        for (int j = 0; j < dcnt; ++j) {
            uint2 a = g_den_arcs[dbeg + j];
            a.x = (a.x & 0xffff0000u) | (unsigned)g_den_inv[a.x & 0xffffu];
            sda[wbase + j * 32 + lane] = a;
        }
        // ---- bank-stagger sort of this thread's column by ((src&31)-lane)&31 ----
        // Commutative sum => any processing order is exact. At inner iteration i,
        // lane l then reads pd bank ~ (l + 32*i/c) mod 32: staggered diagonal,
        // near-conflict-free across the warp.
        for (int j = 1; j < dcnt; ++j) {
            uint2 key = sda[wbase + j * 32 + lane];
            unsigned kb = ((key.x & 31u) + 32u - (unsigned)lane) & 31u;
            int i2 = j - 1;
            while (i2 >= 0) {
                uint2 c2 = sda[wbase + i2 * 32 + lane];
                unsigned cb = ((c2.x & 31u) + 32u - (unsigned)lane) & 31u;
                if (cb <= kb) break;
                sda[wbase + (i2 + 1) * 32 + lane] = c2;
                --i2;
            }
            sda[wbase + (i2 + 1) * 32 + lane] = key;
        }
    }

    // ---- stage num arcs (row-major, small) ----
    int nbase = g_num_rowptr[gb][half * NHALF];
    int ncnt  = g_num_rowptr[gb][(half + 1) * NHALF] - nbase;
    int nstage = (ncnt < CAP_N) ? ncnt : CAP_N;
    for (int i = tid; i < nstage; i += FWD_THREADS) sna[i] = g_num_arcs[gb * NARCS + nbase + i];
    if (tid < 4) sna[nstage + tid] = make_uint2(0u, 0u);
    bool n_insmem = (nend - nbase) <= CAP_N;

    cl.sync();

    int Ed = 0, En = 0;
    const uint2* dacol = sda + wbase + lane;   // this thread's column base

    for (int t = 0; t < Tb; ++t) {
        int par = t & 1;
        // prefetch llh row t+1
        float pf0 = 0.f, pf1 = 0.f, pf2 = 0.f, pf3 = 0.f;
        bool havef = (t + 1 < Tb);
        if (havef) {
            const float* lrow = llh + (size_t)(t + 1) * CC;
            pf0 = __ldg(&lrow[tid]);
            pf1 = __ldg(&lrow[tid + FWD_THREADS]);
            pf2 = __ldg(&lrow[tid + 2 * FWD_THREADS]);
            if (tid < CC - 3 * FWD_THREADS) pf3 = __ldg(&lrow[tid + 3 * FWD_THREADS]);
        }

        // period-4 exact 2^k rescale
        float invd = 1.0f, invn = 1.0f;
        if ((t & 3) == 0) {
            int sl = (t >> 2) & 1;
            float md = fmaxf(fmaxf(pmax[sl * 4 + 0], pmax[sl * 4 + 1]),
                             fmaxf(pmax[sl * 4 + 2], pmax[sl * 4 + 3]));
            float mn = fmaxf(bcn[sl * 2 + 0], bcn[sl * 2 + 1]);
            int ed = (md > 0.f) ? ((int)(__float_as_uint(md) >> 23) - 127) : 0;
            int en = (mn > 0.f) ? ((int)(__float_as_uint(mn) >> 23) - 127) : 0;
            invd = __uint_as_float((unsigned)(127 - ed) << 23);
            invn = __uint_as_float((unsigned)(127 - en) << 23);
            Ed += ed; En += en;
        }

        const float* pdc = pd + par * DSTATES;
        const float* frc = fr + par * CC;

        // ---- den arc loop: conflict-free col-major reads, bank-staggered gathers ----
        float outv = 0.f;
        if (tid < SLICE) {
            float acc0 = 0.f, acc1 = 0.f, acc2 = 0.f, acc3 = 0.f;
            if (d_insmem) {
                for (int i = 0; i < dcnt; i += 4) {
                    uint2 a0 = dacol[(i + 0) * 32];
                    uint2 a1 = dacol[(i + 1) * 32];
                    uint2 a2 = dacol[(i + 2) * 32];
                    uint2 a3 = dacol[(i + 3) * 32];
                    float e0 = __uint_as_float(a0.y);
                    float e1 = (i + 1 < dcnt) ? __uint_as_float(a1.y) : 0.f;
                    float e2 = (i + 2 < dcnt) ? __uint_as_float(a2.y) : 0.f;
                    float e3 = (i + 3 < dcnt) ? __uint_as_float(a3.y) : 0.f;
                    acc0 = fmaf(pdc[a0.x & 0xffffu] * frc[a0.x >> 16], e0, acc0);
                    acc1 = fmaf(pdc[a1.x & 0xffffu] * frc[a1.x >> 16], e1, acc1);
                    acc2 = fmaf(pdc[a2.x & 0xffffu] * frc[a2.x >> 16], e2, acc2);
                    acc3 = fmaf(pdc[a3.x & 0xffffu] * frc[a3.x >> 16], e3, acc3);
                }
            } else {
                for (int i = dbeg; i < dend; ++i) {
                    uint2 a0 = __ldg(&g_den_arcs[i]);
                    int sn_ = g_den_inv[a0.x & 0xffffu];
                    acc0 = fmaf(pdc[sn_] * frc[a0.x >> 16], __uint_as_float(a0.y), acc0);
                }
            }
            outv = (((acc0 + acc1) + (acc2 + acc3))) * invd;
            int off = SM_PD + (par ^ 1) * DSTATES + mynew;
            pd[(par ^ 1) * DSTATES + mynew] = outv;       // own copy: plain STS
            #pragma unroll
            for (int r = 0; r < CLUSTER; ++r)
                if (r != (int)rank) rb[r][off] = outv;    // 3 remote pushes
        }

        // ---- numerator arc loop ----
        float av = 0.f;
        if (tid < NHALF) {
            const float* pnc = pn + par * NSTATES;
            float a0 = 0.f, a1 = 0.f;
            if (n_insmem) {
                const uint2* na = sna - nbase;
                for (int i = nbeg; i < nend; i += 4) {
                    uint2 b0 = na[i];
                    uint2 b1 = na[i + 1];
                    uint2 b2 = na[i + 2];
                    uint2 b3 = na[i + 3];
                    float e0 = __uint_as_float(b0.y);
                    float e1 = (i + 1 < nend) ? __uint_as_float(b1.y) : 0.f;
                    float e2 = (i + 2 < nend) ? __uint_as_float(b2.y) : 0.f;
                    float e3 = (i + 3 < nend) ? __uint_as_float(b3.y) : 0.f;
                    a0 = fmaf(pnc[b0.x & 0xffffu] * frc[b0.x >> 16], e0, a0);
                    a1 = fmaf(pnc[b1.x & 0xffffu] * frc[b1.x >> 16], e1, a1);
                    a0 = fmaf(pnc[b2.x & 0xffffu] * frc[b2.x >> 16], e2, a0);
                    a1 = fmaf(pnc[b3.x & 0xffffu] * frc[b3.x >> 16], e3, a1);
                }
            } else {
                const uint2* na = g_num_arcs + gb * NARCS;
                for (int i = nbeg; i < nend; ++i) {
                    uint2 b0 = __ldg(&na[i]);
                    a0 = fmaf(pnc[b0.x & 0xffffu] * frc[b0.x >> 16], __uint_as_float(b0.y), a0);
                }
            }
            av = (a0 + a1) * invn;
            int off = SM_PN + (par ^ 1) * NSTATES + nst;
            pn[(par ^ 1) * NSTATES + nst] = av;           // own: plain STS
            rb[prank][off] = av;                          // partner remote
        }

        // ---- stage frame t+1 locally ----
        if (havef) {
            float* fn = fr + ((t + 1) & 1) * CC;
            fn[tid]                   = __expf(pf0);
            fn[tid + FWD_THREADS]     = __expf(pf1);
            fn[tid + 2 * FWD_THREADS] = __expf(pf2);
            if (tid < CC - 3 * FWD_THREADS) fn[tid + 3 * FWD_THREADS] = __expf(pf3);
        }

        // ---- max partials every 4th step ----
        bool domax = ((t & 3) == 3);
        if (domax) {
            float vd = outv, vn = av;
            #pragma unroll
            for (int o = 16; o; o >>= 1) {
                vd = fmaxf(vd, __shfl_xor_sync(0xffffffffu, vd, o));
                vn = fmaxf(vn, __shfl_xor_sync(0xffffffffu, vn, o));
            }
            if (lane == 0) { redd[wid] = vd; redn[wid] = vn; }
            __syncthreads();
            if (tid < 32) {
                float md2 = (tid < NWARPS) ? redd[tid] : 0.f;
                float mn2 = (tid < NWARPS) ? redn[tid] : 0.f;
                #pragma unroll
                for (int o = 16; o; o >>= 1) {
                    md2 = fmaxf(md2, __shfl_xor_sync(0xffffffffu, md2, o));
                    mn2 = fmaxf(mn2, __shfl_xor_sync(0xffffffffu, mn2, o));
                }
                if (tid == 0) {
                    int q = ((t >> 2) + 1) & 1;
                    pmax[q * 4 + (int)rank] = md2;
                    #pragma unroll
                    for (int r = 0; r < CLUSTER; ++r)
                        if (r != (int)rank) rb[r][SM_PMAX + q * 4 + (int)rank] = md2;
                    bcn[q * 2 + half] = mn2;
                    rb[prank][SM_BCN + q * 2 + half] = mn2;
                }
            }
        }

        asm volatile("barrier.cluster.arrive.aligned;" ::: "memory");
        asm volatile("barrier.cluster.wait.aligned;" ::: "memory");
    }

    // ---- finals ----
    const float* pdf = pd + (Tb & 1) * DSTATES;
    float sd = 0.f, sn = 0.f;
    for (int i = tid; i < DSTATES; i += FWD_THREADS)
        sd += pdf[i] * __expf(den_final[g_den_order[i]]);
    if (rank < 2 && tid < NSTATES)
        sn = pn[(Tb & 1) * NSTATES + tid] * __expf(num_final[gb * NSTATES + tid]);
    #pragma unroll
    for (int o = 16; o; o >>= 1) {
        sd += __shfl_xor_sync(0xffffffffu, sd, o);
        sn += __shfl_xor_sync(0xffffffffu, sn, o);
    }
    if (lane == 0) { redd[wid] = sd; redn[wid] = sn; }
    __syncthreads();
    if (tid == 0) {
        float totd = 0.f, totn = 0.f;
        for (int w = 0; w < NWARPS; ++w) { totd += redd[w]; totn += redn[w]; }
        if (rank == 0)
            g_denZ[pair] = (totd > 0.f)
                ? (float)((double)Ed * LN2 + log((double)totd)) : -1e30f;
        if (rank < 2)
            g_numZ[s][g][b] = (totn > 0.f)
                ? (float)((double)En * LN2 + log((double)totn)) : -1e30f;
    }
}

// ---------------- finalize ----------------
__global__ void k_finalize(float* __restrict__ out) {
    int b = threadIdx.x;
    float loss = 0.f;
    if (b < BB) {
        float p0 = g_numZ[0][0][b] + g_numZ[1][1][b];
        float p1 = g_numZ[0][1][b] + g_numZ[1][0][b];
        float n0, n1;
        if (p1 > p0) { n0 = g_numZ[0][1][b]; n1 = g_numZ[1][0][b]; }
        else         { n0 = g_numZ[0][0][b]; n1 = g_numZ[1][1][b]; }
        loss = -(n0 - g_denZ[b]) - (n1 - g_denZ[BB + b]);
    }
    #pragma unroll
    for (int o = 16; o; o >>= 1) loss += __shfl_xor_sync(0xffffffffu, loss, o);
    if (b == 0) out[0] = loss;
}

// ---------------- launch ----------------
extern "C" void kernel_launch(void* const* d_in, const int* in_sizes, int n_in,
                              void* d_out, int out_size) {
    const float* est    = (const float*)d_in[0];
    const int*   seqlen = (const int*)  d_in[1];
    const int*   nsrc   = (const int*)  d_in[2];
    const int*   ndst   = (const int*)  d_in[3];
    const int*   nlab   = (const int*)  d_in[4];
    const float* nw     = (const float*)d_in[5];
    const float* nst    = (const float*)d_in[6];
    const float* nfi    = (const float*)d_in[7];
    const int*   dsrc   = (const int*)  d_in[8];
    const int*   ddst   = (const int*)  d_in[9];
    const int*   dlab   = (const int*)  d_in[10];
    const float* dw     = (const float*)d_in[11];
    const float* dst0   = (const float*)d_in[12];
    const float* dfin   = (const float*)d_in[13];
    float* out = (float*)d_out;

    k_prep_zero<<<(DSTATES + 255) / 256, 256>>>();
    k_den_hist <<<(DARCS + 255) / 256, 256>>>(ddst);
    k_prep_rest<<<1 + NPAIR, 1024>>>(dsrc, ddst, dlab, dw, nsrc, ndst, nlab, nw);

    cudaFuncSetAttribute(k_forward, cudaFuncAttributeMaxDynamicSharedMemorySize,
                         SMEM_FWD_BYTES);
    k_forward<<<NPAIR * CLUSTER, FWD_THREADS, SMEM_FWD_BYTES>>>(
        est, seqlen, dst0, dfin, nst, nfi);

    k_finalize<<<1, 32>>>(out);
}

// round 13
// speedup vs baseline: 1.1438x; 1.1438x over previous
#include <cuda_runtime.h>
#include <cuda_bf16.h>
#include <cooperative_groups.h>
#include <math.h>

namespace cg = cooperative_groups;

#define S_SPK   2
#define BB      16
#define TT      300
#define CC      3000
#define NSTATES 400
#define NARCS   1200
#define DSTATES 3000
#define DARCS   60000
#define NPAIR   (S_SPK * BB)        // 32
#define CLUSTER 4
#define SLICE   (DSTATES / CLUSTER) // 750
#define FWD_THREADS 768
#define NWARPS  (FWD_THREADS / 32)  // 24
#define NHALF   (NSTATES / 2)       // 200
#define CAP_D   18432               // smem arc cache cap (den slice, padded col-major)
#define CAP_N   1024                // smem arc cache cap (num half)
#define LN2 0.6931471805599453

// encode float in (0.133,1] to 8 bits: 2 exp LSBs (biased 124..127) + 6 mantissa MSBs, RTN
__device__ __forceinline__ unsigned enc_w8(unsigned fbits) {
    unsigned r = fbits + 0x10000u;                      // round at bit16
    return ((((r >> 23) & 0xFFu) - 124u) << 6) | ((r >> 17) & 0x3Fu);
}

// ---------------- device scratch (static globals, no allocation) ----------------
__device__ int   g_den_hist[DSTATES];
__device__ int   g_den_rowptr[DSTATES + 1];
__device__ uint2 g_den_arcs[DARCS + 4];              // +4 zeroed pad
__device__ int   g_den_order[DSTATES];               // newid -> oldid (desc arc count per slice)
__device__ int   g_den_inv[DSTATES];                 // oldid -> newid

__device__ int   g_num_rowptr[NPAIR][NSTATES + 1];
__device__ uint2 g_num_arcs[NPAIR * NARCS + 4];      // +4 zeroed pad

__device__ float g_denZ[NPAIR];              // [s*BB + b]
__device__ float g_numZ[S_SPK][S_SPK][BB];   // [speaker s][graph g][b]

// ---------------- prep kernel 1: zero hist + pads ----------------
__global__ void k_prep_zero() {
    int i = blockIdx.x * blockDim.x + threadIdx.x;
    if (i < DSTATES) g_den_hist[i] = 0;
    if (i < 4) {
        g_den_arcs[DARCS + i] = make_uint2(0u, 0u);
        g_num_arcs[NPAIR * NARCS + i] = make_uint2(0u, 0u);
    }
}

// ---------------- prep kernel 2: den histogram ----------------
__global__ void k_den_hist(const int* __restrict__ dst) {
    int i = blockIdx.x * blockDim.x + threadIdx.x;
    if (i < DARCS) atomicAdd(&g_den_hist[dst[i]], 1);
}

// ---------------- prep kernel 3 (fused): den scan+scatter+order (CTA 0) + num prep ----
__global__ void __launch_bounds__(1024, 1)
k_prep_rest(const int* __restrict__ dsrc, const int* __restrict__ ddst,
            const int* __restrict__ dlab, const float* __restrict__ dw,
            const int* __restrict__ nsrc, const int* __restrict__ ndst,
            const int* __restrict__ nlab, const float* __restrict__ nw) {
    int tid = threadIdx.x;
    if (blockIdx.x == 0) {
        __shared__ int ssum[1024];
        __shared__ int cur[DSTATES];
        __shared__ int hist4[4 * 128];
        __shared__ int cur4[4 * 128];
        int base = tid * 3;
        int a = 0, b = 0, c = 0;
        if (base     < DSTATES) a = g_den_hist[base];
        if (base + 1 < DSTATES) b = g_den_hist[base + 1];
        if (base + 2 < DSTATES) c = g_den_hist[base + 2];
        int local = a + b + c;
        ssum[tid] = local;
        __syncthreads();
        for (int off = 1; off < 1024; off <<= 1) {
            int v = (tid >= off) ? ssum[tid - off] : 0;
            __syncthreads();
            ssum[tid] += v;
            __syncthreads();
        }
        int excl = ssum[tid] - local;
        if (base < DSTATES)     { g_den_rowptr[base]     = excl;         cur[base]     = excl; }
        if (base + 1 < DSTATES) { g_den_rowptr[base + 1] = excl + a;     cur[base + 1] = excl + a; }
        if (base + 2 < DSTATES) { g_den_rowptr[base + 2] = excl + a + b; cur[base + 2] = excl + a + b; }
        if (tid == 1023) g_den_rowptr[DSTATES] = ssum[1023];
        if (tid < 512) { hist4[tid] = 0; }
        __syncthreads();
        for (int i = tid; i < DARCS; i += 1024) {
            int d = ddst[i];
            int pos = atomicAdd(&cur[d], 1);
            g_den_arcs[pos] = make_uint2((unsigned)dsrc[i] | ((unsigned)dlab[i] << 16),
                                         __float_as_uint(expf(dw[i])));
        }
        for (int i = tid; i < DSTATES; i += 1024) {
            int cnt = g_den_rowptr[i + 1] - g_den_rowptr[i];
            if (cnt > 127) cnt = 127;
            int slc = i / SLICE;
            atomicAdd(&hist4[slc * 128 + (127 - cnt)], 1);
        }
        __syncthreads();
        if (tid < 4) {
            int acc = 0;
            for (int k = 0; k < 128; ++k) { cur4[tid * 128 + k] = acc; acc += hist4[tid * 128 + k]; }
        }
        __syncthreads();
        for (int i = tid; i < DSTATES; i += 1024) {
            int cnt = g_den_rowptr[i + 1] - g_den_rowptr[i];
            if (cnt > 127) cnt = 127;
            int slc = i / SLICE;
            int pos = atomicAdd(&cur4[slc * 128 + (127 - cnt)], 1);
            int newid = slc * SLICE + pos;
            g_den_order[newid] = i;
            g_den_inv[i] = newid;
        }
    } else {
        int gb = blockIdx.x - 1;
        const int*   s_ = nsrc + gb * NARCS;
        const int*   d_ = ndst + gb * NARCS;
        const int*   l_ = nlab + gb * NARCS;
        const float* w_ = nw   + gb * NARCS;
        __shared__ int hist[1024];
        __shared__ int scan2[1024];
        __shared__ int ncur[NSTATES];
        hist[tid] = 0;
        __syncthreads();
        for (int i = tid; i < NARCS; i += 1024) atomicAdd(&hist[d_[i]], 1);
        __syncthreads();
        int local = hist[tid];
        scan2[tid] = local;
        __syncthreads();
        for (int off = 1; off < 1024; off <<= 1) {
            int v = (tid >= off) ? scan2[tid - off] : 0;
            __syncthreads();
            scan2[tid] += v;
            __syncthreads();
        }
        int excl = scan2[tid] - local;
        if (tid < NSTATES) { g_num_rowptr[gb][tid] = excl; ncur[tid] = excl; }
        if (tid == NSTATES) g_num_rowptr[gb][NSTATES] = NARCS;
        __syncthreads();
        for (int i = tid; i < NARCS; i += 1024) {
            int d = d_[i];
            int pos = atomicAdd(&ncur[d], 1);
            g_num_arcs[gb * NARCS + pos] =
                make_uint2((unsigned)s_[i] | ((unsigned)l_[i] << 16), __float_as_uint(expf(w_[i])));
        }
    }
}

// ---------------- fused forward ----------------
// dynamic smem layout (float indices; arc caches are 4B uints):
#define SM_PD    0                        // [2][DSTATES]   (NEW state numbering)
#define SM_FR    (2 * DSTATES)            // [2][CC]
#define SM_PN    (SM_FR + 2 * CC)         // [2][NSTATES]
#define SM_REDD  (SM_PN + 2 * NSTATES)    // [24]
#define SM_REDN  (SM_REDD + 24)           // [24]
#define SM_PMAX  (SM_REDN + 24)           // [2][4]
#define SM_BCN   (SM_PMAX + 8)            // [2][2]
#define SM_WB    (SM_BCN + 4)             // [NWARPS+2]  warp col-major bases (+total)
#define SM_DARC  (SM_WB + NWARPS + 2)     // uint[CAP_D] col-major warp-interleaved
#define SM_NARC  (SM_DARC + CAP_D)        // uint[CAP_N+4]
#define SM_FLOATS (SM_NARC + CAP_N + 4)
#define SMEM_FWD_BYTES (SM_FLOATS * 4)

__global__ void __launch_bounds__(FWD_THREADS, 1) __cluster_dims__(CLUSTER, 1, 1)
k_forward(const float* __restrict__ llhs, const int* __restrict__ seqlen,
          const float* __restrict__ den_start, const float* __restrict__ den_final,
          const float* __restrict__ num_start, const float* __restrict__ num_final) {
    extern __shared__ float sm[];
    float* pd   = sm + SM_PD;
    float* fr   = sm + SM_FR;
    float* pn   = sm + SM_PN;
    float* redd = sm + SM_REDD;
    float* redn = sm + SM_REDN;
    float* pmax = sm + SM_PMAX;
    float* bcn  = sm + SM_BCN;
    int*   wb   = (int*)(sm + SM_WB);
    unsigned* sda = (unsigned*)(sm + SM_DARC);
    unsigned* sna = (unsigned*)(sm + SM_NARC);

    cg::cluster_group cl = cg::this_cluster();
    unsigned rank = cl.block_rank();
    int pair = blockIdx.x >> 2;
    int s = pair >> 4, b = pair & 15;
    const float* llh = llhs + (size_t)pair * TT * CC;
    int Tb = seqlen[b];
    int tid = threadIdx.x;
    int lane = tid & 31, wid = tid >> 5;
    int g    = (int)rank & 1;
    int half = (int)rank >> 1;
    int gb   = g * BB + b;
    int prank = (int)rank ^ 2;

    float* rb[CLUSTER];
    #pragma unroll
    for (int r = 0; r < CLUSTER; ++r) rb[r] = cl.map_shared_rank(sm, r);

    // ---- prologue ----
    for (int i = tid; i < DSTATES; i += FWD_THREADS)
        pd[i] = __expf(den_start[g_den_order[i]]);
    for (int i = tid; i < NSTATES; i += FWD_THREADS)
        pn[i] = __expf(num_start[gb * NSTATES + i]);
    if (tid < 8) pmax[tid] = 1.0f;
    if (tid < 4) bcn[tid]  = 1.0f;
    for (int i = tid; i < CC; i += FWD_THREADS) fr[i] = __expf(llh[i]);

    int mynew = (int)rank * SLICE + tid;
    int dbeg = 0, dend = 0;
    if (tid < SLICE) {
        int myold = g_den_order[mynew];
        dbeg = g_den_rowptr[myold];
        dend = g_den_rowptr[myold + 1];
    }
    int dcnt = dend - dbeg;              // 0 for tid >= SLICE
    int nst = half * NHALF + tid;
    int nbeg = 0, nend = 0;
    if (tid < NHALF) { nbeg = g_num_rowptr[gb][nst]; nend = g_num_rowptr[gb][nst + 1]; }

    // ---- per-warp column-major layout: maxcount (padded to 4), exclusive scan ----
    int mc = dcnt;
    #pragma unroll
    for (int o = 16; o; o >>= 1) mc = max(mc, __shfl_xor_sync(0xffffffffu, mc, o));
    int mcp = (mc + 3) & ~3;
    if (lane == 0) wb[wid] = mcp;
    __syncthreads();
    if (tid < 32) {
        int v = (tid < NWARPS) ? wb[tid] : 0;
        int x = v;
        #pragma unroll
        for (int o = 1; o < 32; o <<= 1) {
            int y = __shfl_up_sync(0xffffffffu, x, o);
            if (lane >= o) x += y;
        }
        if (tid < NWARPS) wb[tid] = (x - v) * 32;       // base in arc slots
        if (tid == NWARPS - 1) wb[NWARPS] = x * 32;     // total slots
    }
    __syncthreads();
    int wbase = wb[wid];
    int dtotal = wb[NWARPS];
    bool d_insmem = (dtotal <= CAP_D);

    // ---- zero the col-major region (pad slots harmless; tail is count-masked) ----
    if (d_insmem) {
        for (int i = tid; i < dtotal; i += FWD_THREADS) sda[i] = 0u;
    }
    __syncthreads();
    // ---- stage den arcs col-major as 4B: src(new) 12b | lab 12b | w8 8b ----
    if (d_insmem && tid < SLICE) {
        for (int j = 0; j < dcnt; ++j) {
            uint2 a = g_den_arcs[dbeg + j];
            unsigned srcn = (unsigned)g_den_inv[a.x & 0xffffu];
            unsigned lab  = a.x >> 16;
            sda[wbase + j * 32 + lane] = srcn | (lab << 12) | (enc_w8(a.y) << 24);
        }
    }

    // ---- stage num arcs (row-major, 4B compressed) ----
    int nbase = g_num_rowptr[gb][half * NHALF];
    int ncnt  = g_num_rowptr[gb][(half + 1) * NHALF] - nbase;
    int nstage = (ncnt < CAP_N) ? ncnt : CAP_N;
    for (int i = tid; i < nstage; i += FWD_THREADS) {
        uint2 a = g_num_arcs[gb * NARCS + nbase + i];
        sna[i] = (a.x & 0xFFFu) | ((a.x >> 16) << 12) | (enc_w8(a.y) << 24);
    }
    if (tid < 4) sna[nstage + tid] = 0u;
    bool n_insmem = (nend - nbase) <= CAP_N;

    cl.sync();

    int Ed = 0, En = 0;
    const unsigned* dacol = sda + wbase + lane;   // this thread's column base

    for (int t = 0; t < Tb; ++t) {
        int par = t & 1;
        // prefetch llh row t+1
        float pf0 = 0.f, pf1 = 0.f, pf2 = 0.f, pf3 = 0.f;
        bool havef = (t + 1 < Tb);
        if (havef) {
            const float* lrow = llh + (size_t)(t + 1) * CC;
            pf0 = __ldg(&lrow[tid]);
            pf1 = __ldg(&lrow[tid + FWD_THREADS]);
            pf2 = __ldg(&lrow[tid + 2 * FWD_THREADS]);
            if (tid < CC - 3 * FWD_THREADS) pf3 = __ldg(&lrow[tid + 3 * FWD_THREADS]);
        }

        // period-4 exact 2^k rescale
        float invd = 1.0f, invn = 1.0f;
        if ((t & 3) == 0) {
            int sl = (t >> 2) & 1;
            float md = fmaxf(fmaxf(pmax[sl * 4 + 0], pmax[sl * 4 + 1]),
                             fmaxf(pmax[sl * 4 + 2], pmax[sl * 4 + 3]));
            float mn = fmaxf(bcn[sl * 2 + 0], bcn[sl * 2 + 1]);
            int ed = (md > 0.f) ? ((int)(__float_as_uint(md) >> 23) - 127) : 0;
            int en = (mn > 0.f) ? ((int)(__float_as_uint(mn) >> 23) - 127) : 0;
            invd = __uint_as_float((unsigned)(127 - ed) << 23);
            invn = __uint_as_float((unsigned)(127 - en) << 23);
            Ed += ed; En += en;
        }

        const float* pdc = pd + par * DSTATES;
        const float* frc = fr + par * CC;

        // ---- den arc loop: conflict-free col-major 4B reads, quad-batched ----
        float outv = 0.f;
        if (tid < SLICE) {
            float acc0 = 0.f, acc1 = 0.f, acc2 = 0.f, acc3 = 0.f;
            if (d_insmem) {
                for (int i = 0; i < dcnt; i += 4) {
                    unsigned a0 = dacol[(i + 0) * 32];
                    unsigned a1 = dacol[(i + 1) * 32];
                    unsigned a2 = dacol[(i + 2) * 32];
                    unsigned a3 = dacol[(i + 3) * 32];
                    float e0 = __uint_as_float(0x3E000000u | ((a0 >> 24) << 17));
                    float e1 = (i + 1 < dcnt) ? __uint_as_float(0x3E000000u | ((a1 >> 24) << 17)) : 0.f;
                    float e2 = (i + 2 < dcnt) ? __uint_as_float(0x3E000000u | ((a2 >> 24) << 17)) : 0.f;
                    float e3 = (i + 3 < dcnt) ? __uint_as_float(0x3E000000u | ((a3 >> 24) << 17)) : 0.f;
                    acc0 = fmaf(pdc[a0 & 0xFFFu] * frc[(a0 >> 12) & 0xFFFu], e0, acc0);
                    acc1 = fmaf(pdc[a1 & 0xFFFu] * frc[(a1 >> 12) & 0xFFFu], e1, acc1);
                    acc2 = fmaf(pdc[a2 & 0xFFFu] * frc[(a2 >> 12) & 0xFFFu], e2, acc2);
                    acc3 = fmaf(pdc[a3 & 0xFFFu] * frc[(a3 >> 12) & 0xFFFu], e3, acc3);
                }
            } else {
                for (int i = dbeg; i < dend; ++i) {
                    uint2 a0 = __ldg(&g_den_arcs[i]);
                    int sn_ = g_den_inv[a0.x & 0xffffu];
                    acc0 = fmaf(pdc[sn_] * frc[a0.x >> 16], __uint_as_float(a0.y), acc0);
                }
            }
            outv = (((acc0 + acc1) + (acc2 + acc3))) * invd;
            int off = SM_PD + (par ^ 1) * DSTATES + mynew;
            pd[(par ^ 1) * DSTATES + mynew] = outv;       // own copy: plain STS
            #pragma unroll
            for (int r = 0; r < CLUSTER; ++r)
                if (r != (int)rank) rb[r][off] = outv;    // 3 remote pushes
        }

        // ---- numerator arc loop ----
        float av = 0.f;
        if (tid < NHALF) {
            const float* pnc = pn + par * NSTATES;
            float a0 = 0.f, a1 = 0.f;
            if (n_insmem) {
                const unsigned* na = sna - nbase;
                for (int i = nbeg; i < nend; i += 4) {
                    unsigned b0 = na[i];
                    unsigned b1 = na[i + 1];
                    unsigned b2 = na[i + 2];
                    unsigned b3 = na[i + 3];
                    float e0 = __uint_as_float(0x3E000000u | ((b0 >> 24) << 17));
                    float e1 = (i + 1 < nend) ? __uint_as_float(0x3E000000u | ((b1 >> 24) << 17)) : 0.f;
                    float e2 = (i + 2 < nend) ? __uint_as_float(0x3E000000u | ((b2 >> 24) << 17)) : 0.f;
                    float e3 = (i + 3 < nend) ? __uint_as_float(0x3E000000u | ((b3 >> 24) << 17)) : 0.f;
                    a0 = fmaf(pnc[b0 & 0xFFFu] * frc[(b0 >> 12) & 0xFFFu], e0, a0);
                    a1 = fmaf(pnc[b1 & 0xFFFu] * frc[(b1 >> 12) & 0xFFFu], e1, a1);
                    a0 = fmaf(pnc[b2 & 0xFFFu] * frc[(b2 >> 12) & 0xFFFu], e2, a0);
                    a1 = fmaf(pnc[b3 & 0xFFFu] * frc[(b3 >> 12) & 0xFFFu], e3, a1);
                }
            } else {
                const uint2* na = g_num_arcs + gb * NARCS;
                for (int i = nbeg; i < nend; ++i) {
                    uint2 b0 = __ldg(&na[i]);
                    a0 = fmaf(pnc[b0.x & 0xffffu] * frc[b0.x >> 16], __uint_as_float(b0.y), a0);
                }
            }
            av = (a0 + a1) * invn;
            int off = SM_PN + (par ^ 1) * NSTATES + nst;
            pn[(par ^ 1) * NSTATES + nst] = av;           // own: plain STS
            rb[prank][off] = av;                          // partner remote
        }

        // ---- stage frame t+1 locally ----
        if (havef) {
            float* fn = fr + ((t + 1) & 1) * CC;
            fn[tid]                   = __expf(pf0);
            fn[tid + FWD_THREADS]     = __expf(pf1);
            fn[tid + 2 * FWD_THREADS] = __expf(pf2);
            if (tid < CC - 3 * FWD_THREADS) fn[tid + 3 * FWD_THREADS] = __expf(pf3);
        }

        // ---- max partials every 4th step ----
        bool domax = ((t & 3) == 3);
        if (domax) {
            float vd = outv, vn = av;
            #pragma unroll
            for (int o = 16; o; o >>= 1) {
                vd = fmaxf(vd, __shfl_xor_sync(0xffffffffu, vd, o));
                vn = fmaxf(vn, __shfl_xor_sync(0xffffffffu, vn, o));
            }
            if (lane == 0) { redd[wid] = vd; redn[wid] = vn; }
            __syncthreads();
            if (tid < 32) {
                float md2 = (tid < NWARPS) ? redd[tid] : 0.f;
                float mn2 = (tid < NWARPS) ? redn[tid] : 0.f;
                #pragma unroll
                for (int o = 16; o; o >>= 1) {
                    md2 = fmaxf(md2, __shfl_xor_sync(0xffffffffu, md2, o));
                    mn2 = fmaxf(mn2, __shfl_xor_sync(0xffffffffu, mn2, o));
                }
                if (tid == 0) {
                    int q = ((t >> 2) + 1) & 1;
                    pmax[q * 4 + (int)rank] = md2;
                    #pragma unroll
                    for (int r = 0; r < CLUSTER; ++r)
                        if (r != (int)rank) rb[r][SM_PMAX + q * 4 + (int)rank] = md2;
                    bcn[q * 2 + half] = mn2;
                    rb[prank][SM_BCN + q * 2 + half] = mn2;
                }
            }
        }

        asm volatile("barrier.cluster.arrive.aligned;" ::: "memory");
        asm volatile("barrier.cluster.wait.aligned;" ::: "memory");
    }

    // ---- finals ----
    const float* pdf = pd + (Tb & 1) * DSTATES;
    float sd = 0.f, sn = 0.f;
    for (int i = tid; i < DSTATES; i += FWD_THREADS)
        sd += pdf[i] * __expf(den_final[g_den_order[i]]);
    if (rank < 2 && tid < NSTATES)
        sn = pn[(Tb & 1) * NSTATES + tid] * __expf(num_final[gb * NSTATES + tid]);
    #pragma unroll
    for (int o = 16; o; o >>= 1) {
        sd += __shfl_xor_sync(0xffffffffu, sd, o);
        sn += __shfl_xor_sync(0xffffffffu, sn, o);
    }
    if (lane == 0) { redd[wid] = sd; redn[wid] = sn; }
    __syncthreads();
    if (tid == 0) {
        float totd = 0.f, totn = 0.f;
        for (int w = 0; w < NWARPS; ++w) { totd += redd[w]; totn += redn[w]; }
        if (rank == 0)
            g_denZ[pair] = (totd > 0.f)
                ? (float)((double)Ed * LN2 + log((double)totd)) : -1e30f;
        if (rank < 2)
            g_numZ[s][g][b] = (totn > 0.f)
                ? (float)((double)En * LN2 + log((double)totn)) : -1e30f;
    }
}

// ---------------- finalize ----------------
__global__ void k_finalize(float* __restrict__ out) {
    int b = threadIdx.x;
    float loss = 0.f;
    if (b < BB) {
        float p0 = g_numZ[0][0][b] + g_numZ[1][1][b];
        float p1 = g_numZ[0][1][b] + g_numZ[1][0][b];
        float n0, n1;
        if (p1 > p0) { n0 = g_numZ[0][1][b]; n1 = g_numZ[1][0][b]; }
        else         { n0 = g_numZ[0][0][b]; n1 = g_numZ[1][1][b]; }
        loss = -(n0 - g_denZ[b]) - (n1 - g_denZ[BB + b]);
    }
    #pragma unroll
    for (int o = 16; o; o >>= 1) loss += __shfl_xor_sync(0xffffffffu, loss, o);
    if (b == 0) out[0] = loss;
}

// ---------------- launch ----------------
extern "C" void kernel_launch(void* const* d_in, const int* in_sizes, int n_in,
                              void* d_out, int out_size) {
    const float* est    = (const float*)d_in[0];
    const int*   seqlen = (const int*)  d_in[1];
    const int*   nsrc   = (const int*)  d_in[2];
    const int*   ndst   = (const int*)  d_in[3];
    const int*   nlab   = (const int*)  d_in[4];
    const float* nw     = (const float*)d_in[5];
    const float* nst    = (const float*)d_in[6];
    const float* nfi    = (const float*)d_in[7];
    const int*   dsrc   = (const int*)  d_in[8];
    const int*   ddst   = (const int*)  d_in[9];
    const int*   dlab   = (const int*)  d_in[10];
    const float* dw     = (const float*)d_in[11];
    const float* dst0   = (const float*)d_in[12];
    const float* dfin   = (const float*)d_in[13];
    float* out = (float*)d_out;

    k_prep_zero<<<(DSTATES + 255) / 256, 256>>>();
    k_den_hist <<<(DARCS + 255) / 256, 256>>>(ddst);
    k_prep_rest<<<1 + NPAIR, 1024>>>(dsrc, ddst, dlab, dw, nsrc, ndst, nlab, nw);

    cudaFuncSetAttribute(k_forward, cudaFuncAttributeMaxDynamicSharedMemorySize,
                         SMEM_FWD_BYTES);
    k_forward<<<NPAIR * CLUSTER, FWD_THREADS, SMEM_FWD_BYTES>>>(
        est, seqlen, dst0, dfin, nst, nfi);

    k_finalize<<<1, 32>>>(out);
}